// round 1
// baseline (speedup 1.0000x reference)
#include <cuda_runtime.h>

#define N_NODES 500000
#define N_EDGES 16000000

// ---------------- device scratch (static; no allocation) ----------------
__device__ int   g_cnt[N_NODES];       // in-degree per node
__device__ int   g_rowptr[N_NODES];    // CSR row starts (by dst)
__device__ int   g_cur[N_NODES];       // fill cursors
__device__ int   g_col[N_EDGES];       // src ids sorted by dst
__device__ float g_inv[N_NODES];       // 1/max(deg,1)
__device__ float g_pa[(size_t)N_NODES * 8];  // projected features, stride 8 (32B records)
__device__ float g_pb[(size_t)N_NODES * 8];
__device__ float g_h [(size_t)N_NODES * 8];  // hidden features, stride 8
__device__ int   g_bsum[2048];         // block sums for scan

// ---------------- CSR build ----------------
__global__ void k_hist(const int* __restrict__ ei, int E) {
    int e = blockIdx.x * blockDim.x + threadIdx.x;
    if (e < E) atomicAdd(&g_cnt[ei[E + e]], 1);   // ei[E+e] = dst
}

__global__ void k_scan1(int nblocks) {
    __shared__ int s[256];
    int i = blockIdx.x * 256 + threadIdx.x;
    int c = (i < N_NODES) ? g_cnt[i] : 0;
    s[threadIdx.x] = c; __syncthreads();
    #pragma unroll
    for (int off = 128; off; off >>= 1) {
        if (threadIdx.x < off) s[threadIdx.x] += s[threadIdx.x + off];
        __syncthreads();
    }
    if (threadIdx.x == 0) g_bsum[blockIdx.x] = s[0];
}

// single block: exclusive scan of block sums (nblocks <= 2048)
__global__ void k_scan2(int nblocks) {
    __shared__ int s[256];
    int t = threadIdx.x;
    int vals[8]; int loc = 0;
    #pragma unroll
    for (int k = 0; k < 8; k++) {
        int idx = t * 8 + k;
        int v = (idx < nblocks) ? g_bsum[idx] : 0;
        vals[k] = v; loc += v;
    }
    s[t] = loc; __syncthreads();
    for (int off = 1; off < 256; off <<= 1) {
        int v = (t >= off) ? s[t - off] : 0;
        __syncthreads();
        s[t] += v;
        __syncthreads();
    }
    int excl = s[t] - loc;
    #pragma unroll
    for (int k = 0; k < 8; k++) {
        int idx = t * 8 + k;
        if (idx < nblocks) g_bsum[idx] = excl;
        excl += vals[k];
    }
}

__global__ void k_scan3() {
    __shared__ int s[256];
    int t = threadIdx.x;
    int i = blockIdx.x * 256 + t;
    int c = (i < N_NODES) ? g_cnt[i] : 0;
    s[t] = c; __syncthreads();
    for (int off = 1; off < 256; off <<= 1) {
        int v = (t >= off) ? s[t - off] : 0;
        __syncthreads();
        s[t] += v;
        __syncthreads();
    }
    int excl = s[t] - c + g_bsum[blockIdx.x];
    if (i < N_NODES) {
        g_rowptr[i] = excl;
        g_cur[i]    = excl;
        g_inv[i]    = 1.0f / (float)max(c, 1);
    }
}

__global__ void k_fill(const int* __restrict__ ei, int E) {
    int e = blockIdx.x * blockDim.x + threadIdx.x;
    if (e < E) {
        int dst = ei[E + e];
        int pos = atomicAdd(&g_cur[dst], 1);
        g_col[pos] = ei[e];                       // src
    }
}

// ---------------- initial projection: p1 = x @ Wl1^T (10 -> 5) ----------------
__global__ void k_proj0(const float* __restrict__ x, const float* __restrict__ Wl1,
                        float* __restrict__ p) {
    __shared__ float W[50];
    if (threadIdx.x < 50) W[threadIdx.x] = Wl1[threadIdx.x];
    __syncthreads();
    int i = blockIdx.x * blockDim.x + threadIdx.x;
    if (i >= N_NODES) return;
    float xv[10];
    #pragma unroll
    for (int j = 0; j < 10; j++) xv[j] = x[(size_t)i * 10 + j];
    #pragma unroll
    for (int d = 0; d < 5; d++) {
        float a = 0.f;
        #pragma unroll
        for (int j = 0; j < 10; j++) a += W[d * 10 + j] * xv[j];
        p[(size_t)i * 8 + d] = a;
    }
}

// ---------------- fused layer: gather-mean(p) + h@Wr^T + b, relu, pre-project next p ----------------
// warp per node; PDIM = dims gathered, IN = h dims, OUT = layer out dims,
// POUT = next layer projected dims (0 = none), RELU
template<int PDIM, int IN, int OUT, int POUT, bool RELU>
__global__ void k_agg(const float* __restrict__ p,
                      const float* __restrict__ h, int hstride,
                      float* __restrict__ hout, int hostride,
                      float* __restrict__ pout, int postride,
                      const float* __restrict__ Wr, const float* __restrict__ b,
                      const float* __restrict__ Wln) {
    __shared__ float sWr[OUT * IN];
    __shared__ float sb[OUT];
    __shared__ float sWl[(POUT > 0) ? POUT * OUT : 1];
    int t = threadIdx.x;
    if (t < OUT * IN) sWr[t] = Wr[t];
    if (t < OUT)      sb[t]  = b[t];
    if (POUT > 0 && t < POUT * OUT) sWl[t] = Wln[t];
    __syncthreads();

    int warp = t >> 5, lane = t & 31;
    int i = blockIdx.x * (blockDim.x >> 5) + warp;
    if (i >= N_NODES) return;

    int start = g_rowptr[i];
    int deg   = g_cnt[i];

    float acc[PDIM];
    #pragma unroll
    for (int d = 0; d < PDIM; d++) acc[d] = 0.f;

    for (int j = start + lane; j < start + deg; j += 32) {
        int s = g_col[j];
        if (PDIM == 5) {
            const float4 v = *reinterpret_cast<const float4*>(p + (size_t)s * 8);
            float v4 = p[(size_t)s * 8 + 4];
            acc[0] += v.x; acc[1] += v.y; acc[2] += v.z; acc[3] += v.w;
            acc[PDIM - 1] += v4;
        } else {
            acc[0] += p[s];
        }
    }

    #pragma unroll
    for (int off = 16; off; off >>= 1) {
        #pragma unroll
        for (int d = 0; d < PDIM; d++)
            acc[d] += __shfl_xor_sync(0xffffffffu, acc[d], off);
    }

    float iv = g_inv[i];
    float outv = 0.f;
    if (lane < OUT) {
        outv = acc[lane] * iv + sb[lane];
        #pragma unroll
        for (int j = 0; j < IN; j++)
            outv += sWr[lane * IN + j] * h[(size_t)i * hstride + j];
        if (RELU) outv = fmaxf(outv, 0.f);
        hout[(size_t)i * hostride + lane] = outv;
    }
    if (POUT > 0) {
        float o[OUT];
        #pragma unroll
        for (int d = 0; d < OUT; d++)
            o[d] = __shfl_sync(0xffffffffu, outv, d);
        if (lane < POUT) {
            float pv = 0.f;
            #pragma unroll
            for (int d = 0; d < OUT; d++) pv += sWl[lane * OUT + d] * o[d];
            pout[(size_t)i * postride + lane] = pv;
        }
    }
}

// ---------------- launch ----------------
extern "C" void kernel_launch(void* const* d_in, const int* in_sizes, int n_in,
                              void* d_out, int out_size) {
    const float* x    = (const float*)d_in[0];
    const int*   ei   = (const int*)  d_in[1];
    const float* Wl1  = (const float*)d_in[2];
    const float* Wr1  = (const float*)d_in[3];
    const float* b1   = (const float*)d_in[4];
    const float* Wlm  = (const float*)d_in[5];   // [8,5,5]
    const float* Wrm  = (const float*)d_in[6];   // [8,5,5]
    const float* bm   = (const float*)d_in[7];   // [8,5]
    const float* Wl10 = (const float*)d_in[8];   // [1,5]
    const float* Wr10 = (const float*)d_in[9];   // [1,5]
    const float* b10  = (const float*)d_in[10];  // [1]
    float* out = (float*)d_out;

    void *pa, *pb, *ph, *pcnt;
    cudaGetSymbolAddress(&pa,   g_pa);
    cudaGetSymbolAddress(&pb,   g_pb);
    cudaGetSymbolAddress(&ph,   g_h);
    cudaGetSymbolAddress(&pcnt, g_cnt);
    float* P[2] = { (float*)pa, (float*)pb };
    float* H    = (float*)ph;

    const int E = N_EDGES;
    int eblocks = (E + 255) / 256;
    int nb      = (N_NODES + 255) / 256;   // 1954

    // build CSR (dst-sorted) — done every call; amortized over 10 layers
    cudaMemsetAsync(pcnt, 0, N_NODES * sizeof(int));
    k_hist <<<eblocks, 256>>>(ei, E);
    k_scan1<<<nb, 256>>>(nb);
    k_scan2<<<1, 256>>>(nb);
    k_scan3<<<nb, 256>>>();
    k_fill <<<eblocks, 256>>>(ei, E);

    // p1 = x @ Wl1^T
    k_proj0<<<nb, 256>>>(x, Wl1, P[0]);

    int ablocks = (N_NODES + 7) / 8;   // 8 warps/block, warp per node

    // layer 0: in=x(10), out=5, pre-project with Wl_mid[0]
    k_agg<5, 10, 5, 5, true><<<ablocks, 256>>>(
        P[0], x, 10, H, 8, P[1], 8, Wr1, b1, Wlm + 0 * 25);

    int cur = 1;
    // layers 1..7 (mid layers 0..6), pre-project with next mid Wl
    for (int L = 1; L <= 7; ++L) {
        k_agg<5, 5, 5, 5, true><<<ablocks, 256>>>(
            P[cur], H, 8, H, 8, P[1 - cur], 8,
            Wrm + (L - 1) * 25, bm + (L - 1) * 5, Wlm + L * 25);
        cur = 1 - cur;
    }
    // layer 8 (mid layer 7), pre-project with Wl10 -> scalar p (stride 1)
    k_agg<5, 5, 5, 1, true><<<ablocks, 256>>>(
        P[cur], H, 8, H, 8, P[1 - cur], 1,
        Wrm + 7 * 25, bm + 7 * 5, Wl10);
    cur = 1 - cur;

    // final layer: gather scalar p, out dim 1, no relu, write d_out
    k_agg<1, 5, 1, 0, false><<<ablocks, 256>>>(
        P[cur], H, 8, out, 1, nullptr, 1, Wr10, b10, nullptr);
}

// round 2
// speedup vs baseline: 1.2780x; 1.2780x over previous
#include <cuda_runtime.h>

#define N_NODES 500000
#define N_EDGES 16000000

// ---------------- device scratch (static; no allocation) ----------------
__device__ int   g_cnt[N_NODES];            // in-degree per node
__device__ int2  g_rowdeg[N_NODES];         // (row start, degree)
__device__ int   g_cur[N_NODES];            // fill cursors
__device__ int   g_col[N_EDGES];            // src ids sorted by dst
__device__ float g_pa[(size_t)N_NODES * 8]; // projected features, stride 8 (32B records)
__device__ float g_pb[(size_t)N_NODES * 8];
__device__ float g_h [(size_t)N_NODES * 8]; // hidden features, stride 8
__device__ int   g_bsum[2048];              // block sums for scan

// ---------------- CSR build ----------------
__global__ void k_hist(const int* __restrict__ ei, int E) {
    int e4 = (blockIdx.x * blockDim.x + threadIdx.x) * 4;
    if (e4 < E) {
        int4 d = *reinterpret_cast<const int4*>(ei + E + e4);  // dst
        atomicAdd(&g_cnt[d.x], 1);
        atomicAdd(&g_cnt[d.y], 1);
        atomicAdd(&g_cnt[d.z], 1);
        atomicAdd(&g_cnt[d.w], 1);
    }
}

__global__ void k_scan1(int nblocks) {
    __shared__ int s[256];
    int i = blockIdx.x * 256 + threadIdx.x;
    int c = (i < N_NODES) ? g_cnt[i] : 0;
    s[threadIdx.x] = c; __syncthreads();
    #pragma unroll
    for (int off = 128; off; off >>= 1) {
        if (threadIdx.x < off) s[threadIdx.x] += s[threadIdx.x + off];
        __syncthreads();
    }
    if (threadIdx.x == 0) g_bsum[blockIdx.x] = s[0];
}

// single block: exclusive scan of block sums (nblocks <= 2048)
__global__ void k_scan2(int nblocks) {
    __shared__ int s[256];
    int t = threadIdx.x;
    int vals[8]; int loc = 0;
    #pragma unroll
    for (int k = 0; k < 8; k++) {
        int idx = t * 8 + k;
        int v = (idx < nblocks) ? g_bsum[idx] : 0;
        vals[k] = v; loc += v;
    }
    s[t] = loc; __syncthreads();
    for (int off = 1; off < 256; off <<= 1) {
        int v = (t >= off) ? s[t - off] : 0;
        __syncthreads();
        s[t] += v;
        __syncthreads();
    }
    int excl = s[t] - loc;
    #pragma unroll
    for (int k = 0; k < 8; k++) {
        int idx = t * 8 + k;
        if (idx < nblocks) g_bsum[idx] = excl;
        excl += vals[k];
    }
}

__global__ void k_scan3() {
    __shared__ int s[256];
    int t = threadIdx.x;
    int i = blockIdx.x * 256 + t;
    int c = (i < N_NODES) ? g_cnt[i] : 0;
    s[t] = c; __syncthreads();
    for (int off = 1; off < 256; off <<= 1) {
        int v = (t >= off) ? s[t - off] : 0;
        __syncthreads();
        s[t] += v;
        __syncthreads();
    }
    int excl = s[t] - c + g_bsum[blockIdx.x];
    if (i < N_NODES) {
        g_rowdeg[i] = make_int2(excl, c);
        g_cur[i]    = excl;
    }
}

__global__ void k_fill(const int* __restrict__ ei, int E) {
    int e4 = (blockIdx.x * blockDim.x + threadIdx.x) * 4;
    if (e4 < E) {
        int4 d = *reinterpret_cast<const int4*>(ei + E + e4);  // dst
        int4 s = *reinterpret_cast<const int4*>(ei + e4);      // src
        int p0 = atomicAdd(&g_cur[d.x], 1); g_col[p0] = s.x;
        int p1 = atomicAdd(&g_cur[d.y], 1); g_col[p1] = s.y;
        int p2 = atomicAdd(&g_cur[d.z], 1); g_col[p2] = s.z;
        int p3 = atomicAdd(&g_cur[d.w], 1); g_col[p3] = s.w;
    }
}

// ---------------- initial projection: p1 = x @ Wl1^T (10 -> 5) ----------------
__global__ void k_proj0(const float* __restrict__ x, const float* __restrict__ Wl1,
                        float* __restrict__ p) {
    __shared__ float W[50];
    if (threadIdx.x < 50) W[threadIdx.x] = Wl1[threadIdx.x];
    __syncthreads();
    int i = blockIdx.x * blockDim.x + threadIdx.x;
    if (i >= N_NODES) return;
    float xv[10];
    #pragma unroll
    for (int j = 0; j < 10; j++) xv[j] = x[(size_t)i * 10 + j];
    #pragma unroll
    for (int d = 0; d < 5; d++) {
        float a = 0.f;
        #pragma unroll
        for (int j = 0; j < 10; j++) a += W[d * 10 + j] * xv[j];
        p[(size_t)i * 8 + d] = a;
    }
}

// ---------------- fused layer ----------------
// gather-mean(p) + h@Wr^T + b, relu, pre-project next p.
// warp per node. PDIM==5 uses (edge,dim) lane mapping: lane = e*5 + d,
// 6 edges per warp-step, 1 L1tex wavefront per edge.
template<int PDIM, int IN, int OUT, int POUT, bool RELU>
__global__ void k_agg(const float* __restrict__ p,
                      const float* __restrict__ h, int hstride,
                      float* __restrict__ hout, int hostride,
                      float* __restrict__ pout, int postride,
                      const float* __restrict__ Wr, const float* __restrict__ b,
                      const float* __restrict__ Wln) {
    __shared__ float sWr[OUT * IN];
    __shared__ float sb[OUT];
    __shared__ float sWl[(POUT > 0) ? POUT * OUT : 1];
    int t = threadIdx.x;
    if (t < OUT * IN) sWr[t] = Wr[t];
    if (t < OUT)      sb[t]  = b[t];
    if (POUT > 0 && t < POUT * OUT) sWl[t] = Wln[t];
    __syncthreads();

    int warp = t >> 5, lane = t & 31;
    int i = blockIdx.x * (blockDim.x >> 5) + warp;
    if (i >= N_NODES) return;

    int2 rd   = g_rowdeg[i];
    int start = rd.x, deg = rd.y, end = start + deg;

    float acc = 0.f;

    if (PDIM == 5) {
        const int e5 = lane / 5;            // 0..5 active, 6 for lanes 30,31
        const int d5 = lane - e5 * 5;       // dim 0..4
        for (int j = start; j < end; j += 30) {
            int cj   = j + lane;
            int cidx = (cj < end) ? g_col[cj] : 0;
            #pragma unroll
            for (int it = 0; it < 5; ++it) {
                int epos = it * 6 + e5;     // <= 30
                int s    = __shfl_sync(0xffffffffu, cidx, epos);
                if (e5 < 6 && (j + epos) < end)
                    acc += __ldg(p + (size_t)s * 8 + d5);
            }
        }
        // reduce 6 edge-groups (stride 5) down to lanes 0..4 (one dim each)
        float v;
        v = __shfl_down_sync(0xffffffffu, acc, 15); if (lane < 15) acc += v;
        v = __shfl_down_sync(0xffffffffu, acc, 10); if (lane < 5)  acc += v;
        v = __shfl_down_sync(0xffffffffu, acc, 5);  if (lane < 5)  acc += v;
    } else {
        // scalar gather, lane per edge
        for (int j = start + lane; j < end; j += 32)
            acc += __ldg(p + g_col[j]);
        #pragma unroll
        for (int off = 16; off; off >>= 1)
            acc += __shfl_xor_sync(0xffffffffu, acc, off);
    }

    // self term: one coalesced load + shfl broadcast
    float hv = (lane < IN) ? h[(size_t)i * hstride + lane] : 0.f;

    float inv  = 1.0f / (float)max(deg, 1);
    float outv = 0.f;
    if (lane < OUT)
        outv = acc * inv + sb[lane];
    #pragma unroll
    for (int j = 0; j < IN; ++j) {
        float hj = __shfl_sync(0xffffffffu, hv, j);
        if (lane < OUT) outv += sWr[lane * IN + j] * hj;
    }
    if (lane < OUT) {
        if (RELU) outv = fmaxf(outv, 0.f);
        hout[(size_t)i * hostride + lane] = outv;
    }

    if (POUT > 0) {
        float pv = 0.f;
        #pragma unroll
        for (int d = 0; d < OUT; ++d) {
            float od = __shfl_sync(0xffffffffu, outv, d);
            if (lane < POUT) pv += sWl[lane * OUT + d] * od;
        }
        if (lane < POUT) pout[(size_t)i * postride + lane] = pv;
    }
}

// ---------------- launch ----------------
extern "C" void kernel_launch(void* const* d_in, const int* in_sizes, int n_in,
                              void* d_out, int out_size) {
    const float* x    = (const float*)d_in[0];
    const int*   ei   = (const int*)  d_in[1];
    const float* Wl1  = (const float*)d_in[2];
    const float* Wr1  = (const float*)d_in[3];
    const float* b1   = (const float*)d_in[4];
    const float* Wlm  = (const float*)d_in[5];   // [8,5,5]
    const float* Wrm  = (const float*)d_in[6];   // [8,5,5]
    const float* bm   = (const float*)d_in[7];   // [8,5]
    const float* Wl10 = (const float*)d_in[8];   // [1,5]
    const float* Wr10 = (const float*)d_in[9];   // [1,5]
    const float* b10  = (const float*)d_in[10];  // [1]
    float* out = (float*)d_out;

    void *pa, *pb, *ph, *pcnt;
    cudaGetSymbolAddress(&pa,   g_pa);
    cudaGetSymbolAddress(&pb,   g_pb);
    cudaGetSymbolAddress(&ph,   g_h);
    cudaGetSymbolAddress(&pcnt, g_cnt);
    float* P[2] = { (float*)pa, (float*)pb };
    float* H    = (float*)ph;

    const int E = N_EDGES;
    int e4blocks = (E / 4 + 255) / 256;
    int nb       = (N_NODES + 255) / 256;   // 1954

    // build CSR (dst-sorted)
    cudaMemsetAsync(pcnt, 0, N_NODES * sizeof(int));
    k_hist <<<e4blocks, 256>>>(ei, E);
    k_scan1<<<nb, 256>>>(nb);
    k_scan2<<<1, 256>>>(nb);
    k_scan3<<<nb, 256>>>();
    k_fill <<<e4blocks, 256>>>(ei, E);

    // p1 = x @ Wl1^T
    k_proj0<<<nb, 256>>>(x, Wl1, P[0]);

    int ablocks = (N_NODES + 7) / 8;   // 8 warps/block, warp per node

    // layer 0: in=x(10), out=5, pre-project with Wl_mid[0]
    k_agg<5, 10, 5, 5, true><<<ablocks, 256>>>(
        P[0], x, 10, H, 8, P[1], 8, Wr1, b1, Wlm + 0 * 25);

    int cur = 1;
    // layers 1..7 (mid layers 0..6), pre-project with next mid Wl
    for (int L = 1; L <= 7; ++L) {
        k_agg<5, 5, 5, 5, true><<<ablocks, 256>>>(
            P[cur], H, 8, H, 8, P[1 - cur], 8,
            Wrm + (L - 1) * 25, bm + (L - 1) * 5, Wlm + L * 25);
        cur = 1 - cur;
    }
    // layer 8 (mid layer 7), pre-project with Wl10 -> scalar p (stride 1)
    k_agg<5, 5, 5, 1, true><<<ablocks, 256>>>(
        P[cur], H, 8, H, 8, P[1 - cur], 1,
        Wrm + 7 * 25, bm + 7 * 5, Wl10);
    cur = 1 - cur;

    // final layer: gather scalar p, out dim 1, no relu, write d_out
    k_agg<1, 5, 1, 0, false><<<ablocks, 256>>>(
        P[cur], H, 8, out, 1, nullptr, 1, Wr10, b10, nullptr);
}